// round 5
// baseline (speedup 1.0000x reference)
#include <cuda_runtime.h>
#include <math.h>

#define VOCAB  32000
#define EMBED  512
#define HIDDEN 1024
#define BATCH  64
#define SEQ    512
#define NG     4096            // 4 * HIDDEN (f,i,g,o packed)
#define M_A    (SEQ * BATCH)   // 32768 rows for the input projection GEMM
#define RCTAS  128

// ---------------- device scratch (static: allocation-guard-safe) ------------
__device__ __align__(128) float g_xproj[M_A * NG];        // 512 MB: x@Wx + bias, layout [t*64+b][col]
__device__ __align__(128) float g_wxP[EMBED * NG];        // Wx packed [k][col], col = g*1024+jh
__device__ __align__(128) float g_whT[NG * HIDDEN];       // Wh packed transposed [col][k]
__device__ __align__(128) float g_bias[NG];
__device__ __align__(128) float g_h[2][HIDDEN * BATCH];   // h double buffer, layout [jh][b]
__device__ __align__(128) int   g_idx[M_A];               // token id per GEMM row
__device__ unsigned g_cnt[SEQ];                           // one barrier counter per step

__device__ __forceinline__ float sigmoidf_(float x) {
    return 1.0f / (1.0f + __expf(-x));
}

// ---------------- prep: pack weights, gather indices, zero state -------------
__global__ void prep_kernel(const int* __restrict__ ids,
                            const float* __restrict__ Wf, const float* __restrict__ bf,
                            const float* __restrict__ Wi, const float* __restrict__ bi,
                            const float* __restrict__ Wc, const float* __restrict__ bc,
                            const float* __restrict__ Wo, const float* __restrict__ bo) {
    int tid = blockIdx.x * blockDim.x + threadIdx.x;
    int nt  = gridDim.x * blockDim.x;

    // Wh transposed: whT[col*1024 + k] = Wg[(512+k)*1024 + jh]
    for (int i = tid; i < NG * HIDDEN; i += nt) {
        int col = i >> 10, k = i & 1023;
        int g = col >> 10, jh = col & 1023;
        const float* W = (g == 0) ? Wf : (g == 1) ? Wi : (g == 2) ? Wc : Wo;
        g_whT[i] = W[(EMBED + k) * HIDDEN + jh];
    }
    // Wx packed: wxP[k*4096 + col] = Wg[k*1024 + jh]
    for (int i = tid; i < EMBED * NG; i += nt) {
        int k = i >> 12, col = i & 4095;
        int g = col >> 10, jh = col & 1023;
        const float* W = (g == 0) ? Wf : (g == 1) ? Wi : (g == 2) ? Wc : Wo;
        g_wxP[i] = W[k * HIDDEN + jh];
    }
    for (int i = tid; i < NG; i += nt) {
        int g = i >> 10, jh = i & 1023;
        const float* b = (g == 0) ? bf : (g == 1) ? bi : (g == 2) ? bc : bo;
        g_bias[i] = b[jh];
    }
    // row m = t*64 + b  ->  token ids[b*SEQ + t]
    for (int i = tid; i < M_A; i += nt)
        g_idx[i] = ids[(i & 63) * SEQ + (i >> 6)];
    for (int i = tid; i < HIDDEN * BATCH; i += nt)
        g_h[0][i] = 0.0f;
    for (int i = tid; i < SEQ; i += nt)
        g_cnt[i] = 0u;
}

// ---------------- phase A: xproj = embed[ids] @ Wx + bias --------------------
// M=32768, N=4096, K=512. CTA tile 128x128, 256 thr, 8x8 per thread, K-chunk 8.
__global__ void __launch_bounds__(256) gemmA_kernel(const float* __restrict__ embed) {
    __shared__ __align__(16) float As[8][128];
    __shared__ __align__(16) float Bs[8][128];
    int tid = threadIdx.x;
    int m0 = blockIdx.y * 128;
    int n0 = blockIdx.x * 128;
    int ty = tid >> 4, tx = tid & 15;

    float acc[8][8];
#pragma unroll
    for (int i = 0; i < 8; i++)
#pragma unroll
        for (int j = 0; j < 8; j++) acc[i][j] = 0.0f;

    int am = tid >> 1;
    int ak = (tid & 1) * 4;
    int arow = g_idx[m0 + am];
    const float* aptr = embed + (size_t)arow * EMBED + ak;
    int bk = tid >> 5;
    int bn = (tid & 31) * 4;

    for (int k0 = 0; k0 < EMBED; k0 += 8) {
        float4 av = *(const float4*)(aptr + k0);
        float4 bv = *(const float4*)(g_wxP + (size_t)(k0 + bk) * NG + n0 + bn);
        __syncthreads();
        As[ak + 0][am] = av.x;
        As[ak + 1][am] = av.y;
        As[ak + 2][am] = av.z;
        As[ak + 3][am] = av.w;
        *(float4*)&Bs[bk][bn] = bv;
        __syncthreads();
#pragma unroll
        for (int kk = 0; kk < 8; kk++) {
            float4 a0 = *(float4*)&As[kk][ty * 8];
            float4 a1 = *(float4*)&As[kk][ty * 8 + 4];
            float4 b0 = *(float4*)&Bs[kk][tx * 8];
            float4 b1 = *(float4*)&Bs[kk][tx * 8 + 4];
            float a[8] = {a0.x, a0.y, a0.z, a0.w, a1.x, a1.y, a1.z, a1.w};
            float b[8] = {b0.x, b0.y, b0.z, b0.w, b1.x, b1.y, b1.z, b1.w};
#pragma unroll
            for (int i = 0; i < 8; i++)
#pragma unroll
                for (int j = 0; j < 8; j++)
                    acc[i][j] = fmaf(a[i], b[j], acc[i][j]);
        }
    }
#pragma unroll
    for (int i = 0; i < 8; i++) {
        size_t ro = (size_t)(m0 + ty * 8 + i) * NG + n0 + tx * 8;
#pragma unroll
        for (int j = 0; j < 8; j++)
            g_xproj[ro + j] = acc[i][j] + g_bias[n0 + tx * 8 + j];
    }
}

// ---------------- phase B: persistent LSTM recurrence ------------------------
// 128 CTAs: cta = (jh_tile<<1) | b_half. Each CTA: 32 b x 16 jh x 4 gates.
__global__ void __launch_bounds__(256) lstm_kernel() {
    __shared__ __align__(16) float Hs[32][32];   // h chunk  [kk][b]
    __shared__ __align__(16) float Ws[32][64];   // Wh chunk [kk][cc]
    __shared__ __align__(16) float Gs[64][32];   // gate preacts [cc][b]
    __shared__ __align__(16) float cs[16][32];   // cell state [u][b] (persistent)

    int tid = threadIdx.x;
    int cta = blockIdx.x;
    int b0 = (cta & 1) * 32;
    int jt = cta >> 1;                // jh base = jt*16
    int bg = tid & 7;                 // b group of 4
    int cg = tid >> 3;                // col group of 2 (cc = cg*2 + j)

    ((float*)cs)[tid] = 0.0f;
    ((float*)cs)[tid + 256] = 0.0f;

    // staging indices
    int h_kk = tid >> 3, h_b4 = (tid & 7) * 4;          // Hs: 32kk x 32b, float4
    int w_cc = tid & 63, w_kq = (tid >> 6) * 8;         // Ws: 64cc x 32kk, 8 k each
    int w_col = (w_cc >> 4) * 1024 + jt * 16 + (w_cc & 15);
    const float* wbase = &g_whT[w_col * HIDDEN];

    for (int t = 0; t < SEQ; t++) {
        const float* hc = g_h[t & 1];
        float* hn = g_h[(t + 1) & 1];

        float acc[4][2];
#pragma unroll
        for (int i = 0; i < 4; i++) { acc[i][0] = 0.0f; acc[i][1] = 0.0f; }

        for (int k0 = 0; k0 < HIDDEN; k0 += 32) {
            float4 hv4 = __ldcg((const float4*)&hc[(k0 + h_kk) * BATCH + b0 + h_b4]);
            float4 w0 = __ldg((const float4*)(wbase + k0 + w_kq));
            float4 w1 = __ldg((const float4*)(wbase + k0 + w_kq + 4));
            __syncthreads();
            *(float4*)&Hs[h_kk][h_b4] = hv4;
            Ws[w_kq + 0][w_cc] = w0.x;
            Ws[w_kq + 1][w_cc] = w0.y;
            Ws[w_kq + 2][w_cc] = w0.z;
            Ws[w_kq + 3][w_cc] = w0.w;
            Ws[w_kq + 4][w_cc] = w1.x;
            Ws[w_kq + 5][w_cc] = w1.y;
            Ws[w_kq + 6][w_cc] = w1.z;
            Ws[w_kq + 7][w_cc] = w1.w;
            __syncthreads();
#pragma unroll
            for (int kk = 0; kk < 32; kk++) {
                float4 hv = *(float4*)&Hs[kk][bg * 4];
                float2 wv = *(float2*)&Ws[kk][cg * 2];
                acc[0][0] = fmaf(hv.x, wv.x, acc[0][0]);
                acc[0][1] = fmaf(hv.x, wv.y, acc[0][1]);
                acc[1][0] = fmaf(hv.y, wv.x, acc[1][0]);
                acc[1][1] = fmaf(hv.y, wv.y, acc[1][1]);
                acc[2][0] = fmaf(hv.z, wv.x, acc[2][0]);
                acc[2][1] = fmaf(hv.z, wv.y, acc[2][1]);
                acc[3][0] = fmaf(hv.w, wv.x, acc[3][0]);
                acc[3][1] = fmaf(hv.w, wv.y, acc[3][1]);
            }
        }

        // add precomputed x-projection (+bias) and stage gate preacts
#pragma unroll
        for (int j = 0; j < 2; j++) {
            int cc = cg * 2 + j;
            int gcol = (cc >> 4) * 1024 + jt * 16 + (cc & 15);
#pragma unroll
            for (int i = 0; i < 4; i++) {
                int bb = bg * 4 + i;
                size_t xo = (size_t)(t * 64 + b0 + bb) * NG + gcol;
                Gs[cc][bb] = acc[i][j] + __ldcs(&g_xproj[xo]);
            }
        }
        __syncthreads();

        // cell/hidden update: 2 cells per thread (cells = 16u x 32b)
#pragma unroll
        for (int e = 0; e < 2; e++) {
            int cell = tid + e * 256;
            int bb = cell & 31, u = cell >> 5;
            float f  = sigmoidf_(Gs[u][bb]);
            float ii = sigmoidf_(Gs[16 + u][bb]);
            float gg = tanhf(Gs[32 + u][bb]);
            float oo = sigmoidf_(Gs[48 + u][bb]);
            float c = cs[u][bb] * f + gg * ii;
            cs[u][bb] = c;
            hn[(jt * 16 + u) * BATCH + b0 + bb] = c * oo;   // no tanh (matches ref)
        }

        // grid-wide barrier (one counter per step; all CTAs resident)
        __threadfence();
        __syncthreads();
        if (tid == 0) {
            atomicAdd(&g_cnt[t], 1u);
            volatile unsigned* p = &g_cnt[t];
            while (*p < (unsigned)RCTAS) { }
        }
        __syncthreads();
    }
}

// ---------------- phase C: logits = h_final @ Wout + bout --------------------
// M=64, N=32000, K=1024. CTA 64x128, 256 thr, 4x8 per thread.
__global__ void __launch_bounds__(256) gemmC_kernel(const float* __restrict__ Wout,
                                                    const float* __restrict__ bout,
                                                    float* __restrict__ out) {
    __shared__ __align__(16) float As[8][64];
    __shared__ __align__(16) float Bs[8][128];
    int tid = threadIdx.x;
    int n0 = blockIdx.x * 128;
    int ty = tid >> 4, tx = tid & 15;

    float acc[4][8];
#pragma unroll
    for (int i = 0; i < 4; i++)
#pragma unroll
        for (int j = 0; j < 8; j++) acc[i][j] = 0.0f;

    int akk = tid >> 5, am = (tid & 31) * 2;
    int bkk = tid >> 5, bn = (tid & 31) * 4;

    for (int k0 = 0; k0 < HIDDEN; k0 += 8) {
        float2 av = *(const float2*)&g_h[0][(k0 + akk) * BATCH + am];  // h[jh][b]
        float4 bv = *(const float4*)(Wout + (size_t)(k0 + bkk) * VOCAB + n0 + bn);
        __syncthreads();
        *(float2*)&As[akk][am] = av;
        *(float4*)&Bs[bkk][bn] = bv;
        __syncthreads();
#pragma unroll
        for (int kk = 0; kk < 8; kk++) {
            float4 a = *(float4*)&As[kk][ty * 4];
            float4 b0 = *(float4*)&Bs[kk][tx * 8];
            float4 b1 = *(float4*)&Bs[kk][tx * 8 + 4];
            float aa[4] = {a.x, a.y, a.z, a.w};
            float bb[8] = {b0.x, b0.y, b0.z, b0.w, b1.x, b1.y, b1.z, b1.w};
#pragma unroll
            for (int i = 0; i < 4; i++)
#pragma unroll
                for (int j = 0; j < 8; j++)
                    acc[i][j] = fmaf(aa[i], bb[j], acc[i][j]);
        }
    }
#pragma unroll
    for (int i = 0; i < 4; i++) {
        int row = ty * 4 + i;
        size_t base = (size_t)row * VOCAB + n0 + tx * 8;
#pragma unroll
        for (int j = 0; j < 8; j++)
            out[base + j] = acc[i][j] + bout[n0 + tx * 8 + j];
    }
}

// ---------------- launcher ---------------------------------------------------
extern "C" void kernel_launch(void* const* d_in, const int* in_sizes, int n_in,
                              void* d_out, int out_size) {
    const int*   ids   = (const int*)d_in[0];
    const float* embed = (const float*)d_in[1];
    const float* Wf    = (const float*)d_in[2];
    const float* bf    = (const float*)d_in[3];
    const float* Wi    = (const float*)d_in[4];
    const float* bi    = (const float*)d_in[5];
    const float* Wc    = (const float*)d_in[6];
    const float* bc    = (const float*)d_in[7];
    const float* Wo    = (const float*)d_in[8];
    const float* bo    = (const float*)d_in[9];
    const float* Wout  = (const float*)d_in[10];
    const float* bout  = (const float*)d_in[11];

    prep_kernel<<<1024, 256>>>(ids, Wf, bf, Wi, bi, Wc, bc, Wo, bo);
    gemmA_kernel<<<dim3(NG / 128, M_A / 128), 256>>>(embed);
    lstm_kernel<<<RCTAS, 256>>>();
    gemmC_kernel<<<VOCAB / 128, 256>>>(Wout, bout, (float*)d_out);
}